// round 13
// baseline (speedup 1.0000x reference)
#include <cuda_runtime.h>
#include <cuda_fp16.h>
#include <cuda_bf16.h>
#include <math.h>

// Problem constants
#define BB 4
#define QQ 16384
#define SS 4
#define HD 256
#define HH 128
#define WW 128
#define HWSZ (HH*WW)          // 16384
#define MTOT (BB*QQ)          // 65536
#define OFFSET_SCALE 0.05f

// ---------------- scratch (device globals; no runtime alloc allowed) ----------
__device__ __half g_fmT[(size_t)BB*HWSZ*HD];  // fmap HWC fp16   33.5MB
__device__ __half g_qh [(size_t)MTOT*HD];     // masked q fp16   33.5MB
__device__ __half g_ctx[(size_t)MTOT*HD];     // ctx_raw (masked) 33.5MB
__device__ __half g_h1 [(size_t)MTOT*HD];     // relu(...)       33.5MB
__device__ float  g_samp[(size_t)MTOT*32];    // per query: 16x (w, offset)  8.4MB
__device__ float  g_wsum[(size_t)MTOT];       // per query bilinear weight sum
__device__ __half g_Wch[512*256];             // [Wq@W1top ; Wf@W1bot] fp16
__device__ __half g_W2h[256*256];
__device__ float  g_cvec[256];                // bq@W1top
__device__ float  g_dvec[256];                // bf@W1bot

// ---------------- mma / ldmatrix / cp.async helpers --------------------------
__device__ __forceinline__ void hmma16(float* c,
                                       unsigned a0, unsigned a1, unsigned a2, unsigned a3,
                                       unsigned b0, unsigned b1) {
    asm volatile(
        "mma.sync.aligned.m16n8k16.row.col.f32.f16.f16.f32 "
        "{%0,%1,%2,%3},{%4,%5,%6,%7},{%8,%9},{%0,%1,%2,%3};"
        : "+f"(c[0]), "+f"(c[1]), "+f"(c[2]), "+f"(c[3])
        : "r"(a0), "r"(a1), "r"(a2), "r"(a3), "r"(b0), "r"(b1));
}
__device__ __forceinline__ void ldsm4(unsigned& r0, unsigned& r1, unsigned& r2, unsigned& r3,
                                      unsigned addr) {
    asm volatile("ldmatrix.sync.aligned.m8n8.x4.shared.b16 {%0,%1,%2,%3}, [%4];"
                 : "=r"(r0), "=r"(r1), "=r"(r2), "=r"(r3) : "r"(addr));
}
__device__ __forceinline__ void ldsm4t(unsigned& r0, unsigned& r1, unsigned& r2, unsigned& r3,
                                       unsigned addr) {
    asm volatile("ldmatrix.sync.aligned.m8n8.x4.trans.shared.b16 {%0,%1,%2,%3}, [%4];"
                 : "=r"(r0), "=r"(r1), "=r"(r2), "=r"(r3) : "r"(addr));
}
__device__ __forceinline__ void cp16(void* dst, const void* src) {
    unsigned d = (unsigned)__cvta_generic_to_shared(dst);
    asm volatile("cp.async.cg.shared.global [%0], [%1], 16;" :: "r"(d), "l"(src));
}
__device__ __forceinline__ void cp_commit() { asm volatile("cp.async.commit_group;"); }
__device__ __forceinline__ void cp_wait0()  { asm volatile("cp.async.wait_group 0;"); }
__device__ __forceinline__ void cp_wait1()  { asm volatile("cp.async.wait_group 1;"); }

#define LDAH 40     // m-major A stride (halfs): 5x16B units -> LDSM conflict-free
#define LDBH 136    // k-major stride (halfs): 17x16B units -> LDSM conflict-free
#define NSTG 3
#define A_STAGE (128*LDAH)
#define B_STAGE (32*LDBH)
#define GEMM_SMEM ((NSTG*(A_STAGE + B_STAGE)) * 2)   // bytes = 56832

// ---------------- merged precompute kernel -----------------------------------
__global__ void __launch_bounds__(256)
prep_kernel(const float* __restrict__ Wq, const float* __restrict__ Wf,
            const float* __restrict__ W1, const float* __restrict__ W2,
            const float* __restrict__ bq, const float* __restrict__ bf,
            __half* __restrict__ oW2, __half* __restrict__ Wcomb,
            float* __restrict__ cvec, float* __restrict__ dvec)
{
    const int bi = blockIdx.x;
    const int t  = threadIdx.x;
    if (bi < 64) {
        const int idx = bi*256 + t;
        float4 v = ((const float4*)W2)[idx];
        ((__half2*)oW2)[idx*2+0] = __floats2half2_rn(v.x, v.y);
        ((__half2*)oW2)[idx*2+1] = __floats2half2_rn(v.z, v.w);
    } else if (bi < 576) {
        const int r = bi - 64;           // 0..511
        const float* arow  = (r < 256) ? (Wq + r*256) : (Wf + (r-256)*256);
        const float* Bbase = (r < 256) ? W1 : (W1 + 256*256);
        __shared__ float a[256];
        a[t] = arow[t];
        __syncthreads();
        float acc = 0.f;
#pragma unroll 4
        for (int k = 0; k < 256; k++) acc = fmaf(a[k], Bbase[k*256 + t], acc);
        Wcomb[r*256 + t] = __float2half_rn(acc);
    } else {
        const float* bv    = (bi == 576) ? bq : bf;
        const float* Bbase = (bi == 576) ? W1 : (W1 + 256*256);
        float* outv        = (bi == 576) ? cvec : dvec;
        float acc = 0.f;
#pragma unroll 4
        for (int k = 0; k < 256; k++) acc = fmaf(bv[k], Bbase[k*256 + t], acc);
        outv[t] = acc;
    }
}

// ---------------- CHW fp32 -> HWC fp16 transpose -----------------------------
__global__ void __launch_bounds__(256)
transpose_h(const float* __restrict__ fm, __half* __restrict__ fmT)
{
    __shared__ float ts[32][33];
    const int b  = blockIdx.z;
    const int c0 = blockIdx.y * 32;
    const int h0 = blockIdx.x * 32;
    const int t  = threadIdx.x;

    {
        const int cl = t >> 3, h4 = (t & 7) * 4;
        float4 v = *(const float4*)(fm + ((size_t)(b*256 + c0 + cl)) * HWSZ + h0 + h4);
        ts[h4+0][cl] = v.x; ts[h4+1][cl] = v.y; ts[h4+2][cl] = v.z; ts[h4+3][cl] = v.w;
    }
    __syncthreads();
    {
        const int hl = t >> 3, c4 = (t & 7) * 4;
        __half2 o0 = __floats2half2_rn(ts[hl][c4+0], ts[hl][c4+1]);
        __half2 o1 = __floats2half2_rn(ts[hl][c4+2], ts[hl][c4+3]);
        __half2* dst = (__half2*)(fmT + ((size_t)((b << 14) + h0 + hl)) * 256 + c0 + c4);
        dst[0] = o0; dst[1] = o1;
    }
}

// ---------------- unified GEMM: 3-stage cp.async, fp16 A ---------------------
template<int MODE, typename TC, bool EXT>
__global__ void __launch_bounds__(256, 2)
gemm_c(const __half* __restrict__ A0, const __half* __restrict__ A1,
       const __half* __restrict__ Wh, const float* __restrict__ Bias,
       const float* __restrict__ cvec, const float* __restrict__ dvec,
       const int* __restrict__ mask, const float* __restrict__ wsum,
       TC* __restrict__ C, int K, int doRelu)
{
    constexpr int N = 256;
    extern __shared__ __half dynsm[];
    __half* AsB = dynsm;
    __half* BsB = dynsm + NSTG * A_STAGE;

    const int t    = threadIdx.x;
    const int m0   = blockIdx.y * 128;
    const int n0   = blockIdx.x * 128;
    const int wid  = t >> 5;
    const int lane = t & 31;
    const int wm   = wid >> 1;
    const int wn   = wid & 1;
    const int g    = lane >> 2;
    const int tig  = lane & 3;

    float acc[2][8][4];
#pragma unroll
    for (int i=0;i<2;i++)
#pragma unroll
        for (int j=0;j<8;j++)
#pragma unroll
            for (int l=0;l<4;l++) acc[i][j][l] = 0.f;

    auto load_tile = [&](int s, int k0) {
        __half* As = AsB + s * A_STAGE;
        __half* Bs = BsB + s * B_STAGE;
#pragma unroll
        for (int i = 0; i < 2; i++) {
            const int idx = t + i * 256;
            const int m   = idx >> 2;
            const int k8  = (idx & 3) * 8;
            const int kg  = k0 + k8;
            const __half* src;
            if (MODE == 2) src = (kg < 256) ? (A0 + (size_t)(m0+m)*256 + kg)
                                            : (A1 + (size_t)(m0+m)*256 + (kg-256));
            else           src = A0 + (size_t)(m0+m)*256 + kg;
            cp16(&As[m*LDAH + k8], src);
        }
#pragma unroll
        for (int i = 0; i < 2; i++) {
            const int idx = t + i * 256;
            const int kr  = idx >> 4;
            const int n8  = (idx & 15) * 8;
            cp16(&Bs[kr*LDBH + n8], Wh + (size_t)(k0+kr)*N + n0 + n8);
        }
        cp_commit();
    };

    auto compute = [&](int s) {
        __half* As = AsB + s * A_STAGE;
        __half* Bs = BsB + s * B_STAGE;
#pragma unroll
        for (int ks = 0; ks < 2; ks++) {
            const int k = ks * 16;
            unsigned a[2][4], b[8][2];
#pragma unroll
            for (int mt = 0; mt < 2; mt++) {
                const int row = wm*32 + mt*16 + (lane & 15);
                const int col = k + ((lane >> 4) << 3);
                unsigned addr = (unsigned)__cvta_generic_to_shared(&As[row*LDAH + col]);
                ldsm4(a[mt][0], a[mt][1], a[mt][2], a[mt][3], addr);
            }
#pragma unroll
            for (int p = 0; p < 4; p++) {
                const int rowB = k + (lane & 15);
                const int colB = wn*64 + p*16 + ((lane >> 4) << 3);
                unsigned addr = (unsigned)__cvta_generic_to_shared(&Bs[rowB*LDBH + colB]);
                ldsm4t(b[2*p][0], b[2*p][1], b[2*p+1][0], b[2*p+1][1], addr);
            }
#pragma unroll
            for (int mt = 0; mt < 2; mt++)
#pragma unroll
                for (int nt = 0; nt < 8; nt++)
                    hmma16(acc[mt][nt], a[mt][0], a[mt][1], a[mt][2], a[mt][3],
                           b[nt][0], b[nt][1]);
        }
    };

    const int nK = K / 32;
    load_tile(0, 0);
    load_tile(1, 32);
    for (int it = 0; it < nK; ++it) {
        if (it + 1 < nK) cp_wait1(); else cp_wait0();
        __syncthreads();
        if (it + 2 < nK) load_tile((it+2)%NSTG, (it+2)*32);
        compute(it % NSTG);
    }

#pragma unroll
    for (int mt = 0; mt < 2; mt++) {
        const int r0 = m0 + wm*32 + mt*16 + g;
        const int r1 = r0 + 8;
        float msk0 = 0.f, msk1 = 0.f, ws0 = 0.f, ws1 = 0.f;
        if (EXT) {
            msk0 = mask[r0] ? 1.f : 0.f;
            msk1 = mask[r1] ? 1.f : 0.f;
            ws0 = wsum[r0]; ws1 = wsum[r1];
        }
#pragma unroll
        for (int nt = 0; nt < 8; nt++) {
            const int c = n0 + wn*64 + nt*8 + tig*2;
            const float bb0 = Bias[c], bb1 = Bias[c+1];
            float v00 = acc[mt][nt][0] + bb0;
            float v01 = acc[mt][nt][1] + bb1;
            float v10 = acc[mt][nt][2] + bb0;
            float v11 = acc[mt][nt][3] + bb1;
            if (EXT) {
                const float cv0 = cvec[c], cv1 = cvec[c+1];
                const float dv0 = dvec[c], dv1 = dvec[c+1];
                v00 += msk0*cv0 + ws0*dv0;  v01 += msk0*cv1 + ws0*dv1;
                v10 += msk1*cv0 + ws1*dv0;  v11 += msk1*cv1 + ws1*dv1;
            }
            if (doRelu) {
                v00 = fmaxf(v00, 0.f); v01 = fmaxf(v01, 0.f);
                v10 = fmaxf(v10, 0.f); v11 = fmaxf(v11, 0.f);
            }
            if constexpr (sizeof(TC) == 2) {
                *(__half2*)((__half*)C + (size_t)r0*N + c) = __floats2half2_rn(v00, v01);
                *(__half2*)((__half*)C + (size_t)r1*N + c) = __floats2half2_rn(v10, v11);
            } else {
                *(float2*)((float*)C + (size_t)r0*N + c) = make_float2(v00, v01);
                *(float2*)((float*)C + (size_t)r1*N + c) = make_float2(v10, v11);
            }
        }
    }
}

// ------------- offsets + softmax + corner precompute + masked qh fp16 --------
__global__ void __launch_bounds__(256)
offw5_kernel(const float* __restrict__ q,
             const float* __restrict__ Wo, const float* __restrict__ bo,
             const float* __restrict__ Ww, const float* __restrict__ bw,
             const float* __restrict__ ref, const int* __restrict__ mask,
             float* __restrict__ samp, float* __restrict__ wsum,
             __half* __restrict__ qh)
{
    __shared__ float wcat[256*12];
    __shared__ float qs[128*33];

    const int t  = threadIdx.x;
    const int q0 = blockIdx.x * 128;

    {
        float4 w0 = *(const float4*)(Wo + t*8);
        float4 w1 = *(const float4*)(Wo + t*8 + 4);
        float4 w2 = *(const float4*)(Ww + t*4);
        *(float4*)&wcat[t*12 + 0] = w0;
        *(float4*)&wcat[t*12 + 4] = w1;
        *(float4*)&wcat[t*12 + 8] = w2;
    }

    float acc[12];
#pragma unroll
    for (int j = 0; j < 12; j++) acc[j] = 0.f;

    for (int k0 = 0; k0 < 256; k0 += 32) {
        __syncthreads();
#pragma unroll
        for (int i = 0; i < 4; i++) {
            const int idx4 = i*256 + t;
            const int row  = idx4 >> 3;
            const int c4   = (idx4 & 7) * 4;
            float4 v = *(const float4*)(q + (size_t)(q0+row)*256 + k0 + c4);
            qs[row*33 + c4 + 0] = v.x; qs[row*33 + c4 + 1] = v.y;
            qs[row*33 + c4 + 2] = v.z; qs[row*33 + c4 + 3] = v.w;
            const float mk = mask[q0+row] ? 1.f : 0.f;
            __half2* dst = (__half2*)(qh + (size_t)(q0+row)*256 + k0 + c4);
            dst[0] = __floats2half2_rn(v.x*mk, v.y*mk);
            dst[1] = __floats2half2_rn(v.z*mk, v.w*mk);
        }
        __syncthreads();
        if (t < 128) {
#pragma unroll
            for (int kk = 0; kk < 32; kk++) {
                const float qv = qs[t*33 + kk];
                const float4 w0 = *(const float4*)&wcat[(k0+kk)*12 + 0];
                const float4 w1 = *(const float4*)&wcat[(k0+kk)*12 + 4];
                const float4 w2 = *(const float4*)&wcat[(k0+kk)*12 + 8];
                acc[0] = fmaf(qv, w0.x, acc[0]); acc[1] = fmaf(qv, w0.y, acc[1]);
                acc[2] = fmaf(qv, w0.z, acc[2]); acc[3] = fmaf(qv, w0.w, acc[3]);
                acc[4] = fmaf(qv, w1.x, acc[4]); acc[5] = fmaf(qv, w1.y, acc[5]);
                acc[6] = fmaf(qv, w1.z, acc[6]); acc[7] = fmaf(qv, w1.w, acc[7]);
                acc[8] = fmaf(qv, w2.x, acc[8]); acc[9] = fmaf(qv, w2.y, acc[9]);
                acc[10]= fmaf(qv, w2.z, acc[10]);acc[11]= fmaf(qv, w2.w, acc[11]);
            }
        }
    }

    if (t < 128) {
        const int qi = q0 + t;
        const float rx = ref[(size_t)qi*2+0];
        const float ry = ref[(size_t)qi*2+1];
        float v[4], mx = -1e30f;
#pragma unroll
        for (int j=0;j<4;j++) { v[j] = acc[8+j] + bw[j]; mx = fmaxf(mx, v[j]); }
        float s = 0.f;
#pragma unroll
        for (int j=0;j<4;j++) { v[j] = __expf(v[j]-mx); s += v[j]; }
        const float inv = 1.f / s;

        float sp[32];
        float wacc = 0.f;
#pragma unroll
        for (int sI=0; sI<4; sI++) {
            const float ox = tanhf(acc[2*sI+0] + bo[2*sI+0]) * OFFSET_SCALE;
            const float oy = tanhf(acc[2*sI+1] + bo[2*sI+1]) * OFFSET_SCALE;
            const float gx = fminf(fmaxf(rx + ox, -1.2f), 1.2f);
            const float gy = fminf(fmaxf(ry + oy, -1.2f), 1.2f);
            const float w  = v[sI] * inv;
            const float x = (gx + 1.f) * 0.5f * (WW - 1);
            const float y = (gy + 1.f) * 0.5f * (HH - 1);
            const float x0f = floorf(x), y0f = floorf(y);
            const int x0 = (int)x0f, y0 = (int)y0f;
            const float wx1 = x - x0f, wy1 = y - y0f;
            const float wx0 = 1.f - wx1, wy0 = 1.f - wy1;
            const int   xs[2]  = {x0, x0+1};
            const int   ys[2]  = {y0, y0+1};
            const float wxs[2] = {wx0, wx1};
            const float wys[2] = {wy0, wy1};
#pragma unroll
            for (int cy=0; cy<2; cy++)
#pragma unroll
                for (int cx=0; cx<2; cx++) {
                    const int c = sI*4 + cy*2 + cx;
                    const int xi = xs[cx], yi = ys[cy];
                    const bool valid = (xi >= 0 && xi < WW && yi >= 0 && yi < HH);
                    const float cw = valid ? (w * wxs[cx] * wys[cy]) : 0.f;
                    const int  off = valid ? ((yi*WW + xi) << 8) : 0;
                    wacc += cw;
                    sp[c*2+0] = cw;
                    sp[c*2+1] = __int_as_float(off);
                }
        }
        wsum[qi] = mask[qi] ? wacc : 0.f;
        float4* dst = (float4*)(samp + (size_t)qi*32);
#pragma unroll
        for (int i = 0; i < 8; i++)
            dst[i] = make_float4(sp[4*i+0], sp[4*i+1], sp[4*i+2], sp[4*i+3]);
    }
}

// ------------- lean gather: ONE query per warp (max TLP) ---------------------
__global__ void __launch_bounds__(256)
sample7_kernel(const __half* __restrict__ fmT, const float* __restrict__ samp,
               const int* __restrict__ mask, __half* __restrict__ ctx)
{
    const int t = threadIdx.x;
    const int wid = t >> 5, lane = t & 31;
    const int d = lane * 8;
    const int qi = blockIdx.x * 8 + wid;

    if (!mask[qi]) {
        uint4 z = make_uint4(0,0,0,0);
        *(uint4*)(ctx + (size_t)qi*256 + d) = z;
        return;
    }

    const float4* spp = (const float4*)(samp + (size_t)qi*32);
    float4 sv[8];
#pragma unroll
    for (int i = 0; i < 8; i++) sv[i] = spp[i];

    const __half* base = fmT + ((((size_t)(qi >> 14)) << 14)) * 256 + d;
    float a8[8] = {0.f,0.f,0.f,0.f,0.f,0.f,0.f,0.f};
#pragma unroll
    for (int c = 0; c < 16; c++) {
        const float4 f = sv[c >> 1];
        const float w  = (c & 1) ? f.z : f.x;
        const int  off = __float_as_int((c & 1) ? f.w : f.y);
        if (w != 0.f) {
            const uint4 vv = *(const uint4*)(base + off);
            const __half2* h = (const __half2*)&vv;
#pragma unroll
            for (int p = 0; p < 4; p++) {
                float2 fv = __half22float2(h[p]);
                a8[2*p+0] = fmaf(w, fv.x, a8[2*p+0]);
                a8[2*p+1] = fmaf(w, fv.y, a8[2*p+1]);
            }
        }
    }

    __half2 o0 = __floats2half2_rn(a8[0], a8[1]);
    __half2 o1 = __floats2half2_rn(a8[2], a8[3]);
    __half2 o2 = __floats2half2_rn(a8[4], a8[5]);
    __half2 o3 = __floats2half2_rn(a8[6], a8[7]);
    uint4 o;
    o.x = *(unsigned*)&o0; o.y = *(unsigned*)&o1;
    o.z = *(unsigned*)&o2; o.w = *(unsigned*)&o3;
    *(uint4*)(ctx + (size_t)qi*256 + d) = o;
}

// -----------------------------------------------------------------------------
extern "C" void kernel_launch(void* const* d_in, const int* in_sizes, int n_in,
                              void* d_out, int out_size)
{
    const float* queries  = (const float*)d_in[0];
    const float* ref_pts  = (const float*)d_in[1];
    const float* fmap     = (const float*)d_in[2];
    const int*   vmask    = (const int*)  d_in[3];
    const float* Wq = (const float*)d_in[4];
    const float* bq = (const float*)d_in[5];
    const float* Wf = (const float*)d_in[6];
    const float* bf = (const float*)d_in[7];
    const float* Wo = (const float*)d_in[8];
    const float* bo = (const float*)d_in[9];
    const float* Ww = (const float*)d_in[10];
    const float* bw = (const float*)d_in[11];
    const float* W1 = (const float*)d_in[12];
    const float* b1 = (const float*)d_in[13];
    const float* W2 = (const float*)d_in[14];
    const float* b2 = (const float*)d_in[15];
    float* out = (float*)d_out;

    __half *fmT, *qh, *ctxh, *h1h, *Wch, *W2h;
    float *samp, *wsum, *cvec, *dvec;
    cudaGetSymbolAddress((void**)&fmT,  g_fmT);
    cudaGetSymbolAddress((void**)&qh,   g_qh);
    cudaGetSymbolAddress((void**)&ctxh, g_ctx);
    cudaGetSymbolAddress((void**)&h1h,  g_h1);
    cudaGetSymbolAddress((void**)&samp, g_samp);
    cudaGetSymbolAddress((void**)&wsum, g_wsum);
    cudaGetSymbolAddress((void**)&Wch,  g_Wch);
    cudaGetSymbolAddress((void**)&W2h,  g_W2h);
    cudaGetSymbolAddress((void**)&cvec, g_cvec);
    cudaGetSymbolAddress((void**)&dvec, g_dvec);

    // one-time setup: smem attr + side streams/events (host-side, no device mem)
    static cudaStream_t sA = nullptr, sB = nullptr;
    static cudaEvent_t evR = nullptr, evA = nullptr, evB = nullptr;
    if (!sA) {
        cudaFuncSetAttribute(gemm_c<2, __half, true>,
                             cudaFuncAttributeMaxDynamicSharedMemorySize, GEMM_SMEM);
        cudaFuncSetAttribute(gemm_c<0, float, false>,
                             cudaFuncAttributeMaxDynamicSharedMemorySize, GEMM_SMEM);
        cudaStreamCreateWithFlags(&sA, cudaStreamNonBlocking);
        cudaStreamCreateWithFlags(&sB, cudaStreamNonBlocking);
        cudaEventCreateWithFlags(&evR, cudaEventDisableTiming);
        cudaEventCreateWithFlags(&evA, cudaEventDisableTiming);
        cudaEventCreateWithFlags(&evB, cudaEventDisableTiming);
    }

    const dim3 gGemm(256/128, MTOT/128);    // (2, 512)
    const dim3 gTr(HWSZ/32, 256/32, BB);    // (512, 8, 4)

    // fork: transpose on sA, prep on sB, offw5 on the main stream
    cudaEventRecord(evR, 0);
    cudaStreamWaitEvent(sA, evR, 0);
    cudaStreamWaitEvent(sB, evR, 0);
    transpose_h<<<gTr, 256, 0, sA>>>(fmap, fmT);
    prep_kernel<<<578, 256, 0, sB>>>(Wq, Wf, W1, W2, bq, bf, W2h, Wch, cvec, dvec);
    offw5_kernel<<<MTOT/128, 256>>>(queries, Wo, bo, Ww, bw, ref_pts, vmask,
                                    samp, wsum, qh);
    // join
    cudaEventRecord(evA, sA);
    cudaEventRecord(evB, sB);
    cudaStreamWaitEvent(0, evA, 0);
    cudaStreamWaitEvent(0, evB, 0);

    // gather -> ctx_raw fp16 (masked); one warp per query
    sample7_kernel<<<MTOT/8, 256>>>(fmT, samp, vmask, ctxh);
    // h1 = relu(qh@Wc + ctx_raw@Wf1 + b1 + m*cvec + wsum*dvec)
    gemm_c<2, __half, true><<<gGemm, 256, GEMM_SMEM>>>(
        qh, ctxh, Wch, b1, cvec, dvec, vmask, wsum, h1h, 512, 1);
    // out = h1 @ W2 + b2
    gemm_c<0, float, false><<<gGemm, 256, GEMM_SMEM>>>(
        h1h, nullptr, W2h, b2, nullptr, nullptr, nullptr, nullptr, out, 256, 0);
}

// round 14
// speedup vs baseline: 1.0696x; 1.0696x over previous
#include <cuda_runtime.h>
#include <cuda_fp16.h>
#include <cuda_bf16.h>
#include <math.h>

// Problem constants
#define BB 4
#define QQ 16384
#define SS 4
#define HD 256
#define HH 128
#define WW 128
#define HWSZ (HH*WW)          // 16384
#define MTOT (BB*QQ)          // 65536
#define OFFSET_SCALE 0.05f

// ---------------- scratch (device globals; no runtime alloc allowed) ----------
__device__ __half g_fmT[(size_t)BB*HWSZ*HD];  // fmap HWC fp16   33.5MB
__device__ __half g_qh [(size_t)MTOT*HD];     // masked q fp16   33.5MB
__device__ __half g_ctx[(size_t)MTOT*HD];     // ctx_raw (masked) 33.5MB
__device__ __half g_h1 [(size_t)MTOT*HD];     // relu(...)       33.5MB
__device__ float  g_samp[(size_t)MTOT*12];    // per query: (gx,gy,w)x4
__device__ float  g_wsum[(size_t)MTOT];       // per query bilinear weight sum
__device__ __half g_Wch[512*256];             // [Wq@W1top ; Wf@W1bot] fp16
__device__ __half g_W2h[256*256];
__device__ float  g_cvec[256];                // bq@W1top
__device__ float  g_dvec[256];                // bf@W1bot

// ---------------- mma / ldmatrix / cp.async helpers --------------------------
__device__ __forceinline__ void hmma16(float* c,
                                       unsigned a0, unsigned a1, unsigned a2, unsigned a3,
                                       unsigned b0, unsigned b1) {
    asm volatile(
        "mma.sync.aligned.m16n8k16.row.col.f32.f16.f16.f32 "
        "{%0,%1,%2,%3},{%4,%5,%6,%7},{%8,%9},{%0,%1,%2,%3};"
        : "+f"(c[0]), "+f"(c[1]), "+f"(c[2]), "+f"(c[3])
        : "r"(a0), "r"(a1), "r"(a2), "r"(a3), "r"(b0), "r"(b1));
}
__device__ __forceinline__ void ldsm4(unsigned& r0, unsigned& r1, unsigned& r2, unsigned& r3,
                                      unsigned addr) {
    asm volatile("ldmatrix.sync.aligned.m8n8.x4.shared.b16 {%0,%1,%2,%3}, [%4];"
                 : "=r"(r0), "=r"(r1), "=r"(r2), "=r"(r3) : "r"(addr));
}
__device__ __forceinline__ void ldsm4t(unsigned& r0, unsigned& r1, unsigned& r2, unsigned& r3,
                                       unsigned addr) {
    asm volatile("ldmatrix.sync.aligned.m8n8.x4.trans.shared.b16 {%0,%1,%2,%3}, [%4];"
                 : "=r"(r0), "=r"(r1), "=r"(r2), "=r"(r3) : "r"(addr));
}
__device__ __forceinline__ void cp16(void* dst, const void* src) {
    unsigned d = (unsigned)__cvta_generic_to_shared(dst);
    asm volatile("cp.async.cg.shared.global [%0], [%1], 16;" :: "r"(d), "l"(src));
}
__device__ __forceinline__ void cp_commit() { asm volatile("cp.async.commit_group;"); }
__device__ __forceinline__ void cp_wait0()  { asm volatile("cp.async.wait_group 0;"); }
__device__ __forceinline__ void cp_wait1()  { asm volatile("cp.async.wait_group 1;"); }

#define LDAH 40     // m-major A stride (halfs): 5x16B units -> LDSM conflict-free
#define LDBH 136    // k-major stride (halfs): 17x16B units -> LDSM conflict-free
#define NSTG 3
#define A_STAGE (128*LDAH)
#define B_STAGE (32*LDBH)
#define GEMM_SMEM ((NSTG*(A_STAGE + B_STAGE)) * 2)   // bytes = 56832

// ---------------- merged precompute kernel -----------------------------------
__global__ void __launch_bounds__(256)
prep_kernel(const float* __restrict__ Wq, const float* __restrict__ Wf,
            const float* __restrict__ W1, const float* __restrict__ W2,
            const float* __restrict__ bq, const float* __restrict__ bf,
            __half* __restrict__ oW2, __half* __restrict__ Wcomb,
            float* __restrict__ cvec, float* __restrict__ dvec)
{
    const int bi = blockIdx.x;
    const int t  = threadIdx.x;
    if (bi < 64) {
        const int idx = bi*256 + t;
        float4 v = ((const float4*)W2)[idx];
        ((__half2*)oW2)[idx*2+0] = __floats2half2_rn(v.x, v.y);
        ((__half2*)oW2)[idx*2+1] = __floats2half2_rn(v.z, v.w);
    } else if (bi < 576) {
        const int r = bi - 64;           // 0..511
        const float* arow  = (r < 256) ? (Wq + r*256) : (Wf + (r-256)*256);
        const float* Bbase = (r < 256) ? W1 : (W1 + 256*256);
        __shared__ float a[256];
        a[t] = arow[t];
        __syncthreads();
        float acc = 0.f;
#pragma unroll 4
        for (int k = 0; k < 256; k++) acc = fmaf(a[k], Bbase[k*256 + t], acc);
        Wcomb[r*256 + t] = __float2half_rn(acc);
    } else {
        const float* bv    = (bi == 576) ? bq : bf;
        const float* Bbase = (bi == 576) ? W1 : (W1 + 256*256);
        float* outv        = (bi == 576) ? cvec : dvec;
        float acc = 0.f;
#pragma unroll 4
        for (int k = 0; k < 256; k++) acc = fmaf(bv[k], Bbase[k*256 + t], acc);
        outv[t] = acc;
    }
}

// ---------------- CHW fp32 -> HWC fp16 transpose -----------------------------
__global__ void __launch_bounds__(256)
transpose_h(const float* __restrict__ fm, __half* __restrict__ fmT)
{
    __shared__ float ts[32][33];
    const int b  = blockIdx.z;
    const int c0 = blockIdx.y * 32;
    const int h0 = blockIdx.x * 32;
    const int t  = threadIdx.x;

    {
        const int cl = t >> 3, h4 = (t & 7) * 4;
        float4 v = *(const float4*)(fm + ((size_t)(b*256 + c0 + cl)) * HWSZ + h0 + h4);
        ts[h4+0][cl] = v.x; ts[h4+1][cl] = v.y; ts[h4+2][cl] = v.z; ts[h4+3][cl] = v.w;
    }
    __syncthreads();
    {
        const int hl = t >> 3, c4 = (t & 7) * 4;
        __half2 o0 = __floats2half2_rn(ts[hl][c4+0], ts[hl][c4+1]);
        __half2 o1 = __floats2half2_rn(ts[hl][c4+2], ts[hl][c4+3]);
        __half2* dst = (__half2*)(fmT + ((size_t)((b << 14) + h0 + hl)) * 256 + c0 + c4);
        dst[0] = o0; dst[1] = o1;
    }
}

// ---------------- unified GEMM: 3-stage cp.async, fp16 A ---------------------
template<int MODE, typename TC, bool EXT>
__global__ void __launch_bounds__(256, 2)
gemm_c(const __half* __restrict__ A0, const __half* __restrict__ A1,
       const __half* __restrict__ Wh, const float* __restrict__ Bias,
       const float* __restrict__ cvec, const float* __restrict__ dvec,
       const int* __restrict__ mask, const float* __restrict__ wsum,
       TC* __restrict__ C, int K, int doRelu)
{
    constexpr int N = 256;
    extern __shared__ __half dynsm[];
    __half* AsB = dynsm;
    __half* BsB = dynsm + NSTG * A_STAGE;

    const int t    = threadIdx.x;
    const int m0   = blockIdx.y * 128;
    const int n0   = blockIdx.x * 128;
    const int wid  = t >> 5;
    const int lane = t & 31;
    const int wm   = wid >> 1;
    const int wn   = wid & 1;
    const int g    = lane >> 2;
    const int tig  = lane & 3;

    float acc[2][8][4];
#pragma unroll
    for (int i=0;i<2;i++)
#pragma unroll
        for (int j=0;j<8;j++)
#pragma unroll
            for (int l=0;l<4;l++) acc[i][j][l] = 0.f;

    auto load_tile = [&](int s, int k0) {
        __half* As = AsB + s * A_STAGE;
        __half* Bs = BsB + s * B_STAGE;
#pragma unroll
        for (int i = 0; i < 2; i++) {
            const int idx = t + i * 256;
            const int m   = idx >> 2;
            const int k8  = (idx & 3) * 8;
            const int kg  = k0 + k8;
            const __half* src;
            if (MODE == 2) src = (kg < 256) ? (A0 + (size_t)(m0+m)*256 + kg)
                                            : (A1 + (size_t)(m0+m)*256 + (kg-256));
            else           src = A0 + (size_t)(m0+m)*256 + kg;
            cp16(&As[m*LDAH + k8], src);
        }
#pragma unroll
        for (int i = 0; i < 2; i++) {
            const int idx = t + i * 256;
            const int kr  = idx >> 4;
            const int n8  = (idx & 15) * 8;
            cp16(&Bs[kr*LDBH + n8], Wh + (size_t)(k0+kr)*N + n0 + n8);
        }
        cp_commit();
    };

    auto compute = [&](int s) {
        __half* As = AsB + s * A_STAGE;
        __half* Bs = BsB + s * B_STAGE;
#pragma unroll
        for (int ks = 0; ks < 2; ks++) {
            const int k = ks * 16;
            unsigned a[2][4], b[8][2];
#pragma unroll
            for (int mt = 0; mt < 2; mt++) {
                const int row = wm*32 + mt*16 + (lane & 15);
                const int col = k + ((lane >> 4) << 3);
                unsigned addr = (unsigned)__cvta_generic_to_shared(&As[row*LDAH + col]);
                ldsm4(a[mt][0], a[mt][1], a[mt][2], a[mt][3], addr);
            }
#pragma unroll
            for (int p = 0; p < 4; p++) {
                const int rowB = k + (lane & 15);
                const int colB = wn*64 + p*16 + ((lane >> 4) << 3);
                unsigned addr = (unsigned)__cvta_generic_to_shared(&Bs[rowB*LDBH + colB]);
                ldsm4t(b[2*p][0], b[2*p][1], b[2*p+1][0], b[2*p+1][1], addr);
            }
#pragma unroll
            for (int mt = 0; mt < 2; mt++)
#pragma unroll
                for (int nt = 0; nt < 8; nt++)
                    hmma16(acc[mt][nt], a[mt][0], a[mt][1], a[mt][2], a[mt][3],
                           b[nt][0], b[nt][1]);
        }
    };

    const int nK = K / 32;
    load_tile(0, 0);
    load_tile(1, 32);
    for (int it = 0; it < nK; ++it) {
        if (it + 1 < nK) cp_wait1(); else cp_wait0();
        __syncthreads();
        if (it + 2 < nK) load_tile((it+2)%NSTG, (it+2)*32);
        compute(it % NSTG);
    }

#pragma unroll
    for (int mt = 0; mt < 2; mt++) {
        const int r0 = m0 + wm*32 + mt*16 + g;
        const int r1 = r0 + 8;
        float msk0 = 0.f, msk1 = 0.f, ws0 = 0.f, ws1 = 0.f;
        if (EXT) {
            msk0 = mask[r0] ? 1.f : 0.f;
            msk1 = mask[r1] ? 1.f : 0.f;
            ws0 = wsum[r0]; ws1 = wsum[r1];
        }
#pragma unroll
        for (int nt = 0; nt < 8; nt++) {
            const int c = n0 + wn*64 + nt*8 + tig*2;
            const float bb0 = Bias[c], bb1 = Bias[c+1];
            float v00 = acc[mt][nt][0] + bb0;
            float v01 = acc[mt][nt][1] + bb1;
            float v10 = acc[mt][nt][2] + bb0;
            float v11 = acc[mt][nt][3] + bb1;
            if (EXT) {
                const float cv0 = cvec[c], cv1 = cvec[c+1];
                const float dv0 = dvec[c], dv1 = dvec[c+1];
                v00 += msk0*cv0 + ws0*dv0;  v01 += msk0*cv1 + ws0*dv1;
                v10 += msk1*cv0 + ws1*dv0;  v11 += msk1*cv1 + ws1*dv1;
            }
            if (doRelu) {
                v00 = fmaxf(v00, 0.f); v01 = fmaxf(v01, 0.f);
                v10 = fmaxf(v10, 0.f); v11 = fmaxf(v11, 0.f);
            }
            if constexpr (sizeof(TC) == 2) {
                *(__half2*)((__half*)C + (size_t)r0*N + c) = __floats2half2_rn(v00, v01);
                *(__half2*)((__half*)C + (size_t)r1*N + c) = __floats2half2_rn(v10, v11);
            } else {
                *(float2*)((float*)C + (size_t)r0*N + c) = make_float2(v00, v01);
                *(float2*)((float*)C + (size_t)r1*N + c) = make_float2(v10, v11);
            }
        }
    }
}

// ------------- offsets + softmax + postprocess + wsum + masked qh fp16 -------
// samp layout: 12 floats per query = (gx, gy, w) x 4  (sample5 format)
__global__ void __launch_bounds__(256)
offw6_kernel(const float* __restrict__ q,
             const float* __restrict__ Wo, const float* __restrict__ bo,
             const float* __restrict__ Ww, const float* __restrict__ bw,
             const float* __restrict__ ref, const int* __restrict__ mask,
             float* __restrict__ samp, float* __restrict__ wsum,
             __half* __restrict__ qh)
{
    __shared__ float wcat[256*12];
    __shared__ float qs[128*33];

    const int t  = threadIdx.x;
    const int q0 = blockIdx.x * 128;

    {
        float4 w0 = *(const float4*)(Wo + t*8);
        float4 w1 = *(const float4*)(Wo + t*8 + 4);
        float4 w2 = *(const float4*)(Ww + t*4);
        *(float4*)&wcat[t*12 + 0] = w0;
        *(float4*)&wcat[t*12 + 4] = w1;
        *(float4*)&wcat[t*12 + 8] = w2;
    }

    float acc[12];
#pragma unroll
    for (int j = 0; j < 12; j++) acc[j] = 0.f;

    for (int k0 = 0; k0 < 256; k0 += 32) {
        __syncthreads();
#pragma unroll
        for (int i = 0; i < 4; i++) {
            const int idx4 = i*256 + t;
            const int row  = idx4 >> 3;
            const int c4   = (idx4 & 7) * 4;
            float4 v = *(const float4*)(q + (size_t)(q0+row)*256 + k0 + c4);
            qs[row*33 + c4 + 0] = v.x; qs[row*33 + c4 + 1] = v.y;
            qs[row*33 + c4 + 2] = v.z; qs[row*33 + c4 + 3] = v.w;
            const float mk = mask[q0+row] ? 1.f : 0.f;
            __half2* dst = (__half2*)(qh + (size_t)(q0+row)*256 + k0 + c4);
            dst[0] = __floats2half2_rn(v.x*mk, v.y*mk);
            dst[1] = __floats2half2_rn(v.z*mk, v.w*mk);
        }
        __syncthreads();
        if (t < 128) {
#pragma unroll
            for (int kk = 0; kk < 32; kk++) {
                const float qv = qs[t*33 + kk];
                const float4 w0 = *(const float4*)&wcat[(k0+kk)*12 + 0];
                const float4 w1 = *(const float4*)&wcat[(k0+kk)*12 + 4];
                const float4 w2 = *(const float4*)&wcat[(k0+kk)*12 + 8];
                acc[0] = fmaf(qv, w0.x, acc[0]); acc[1] = fmaf(qv, w0.y, acc[1]);
                acc[2] = fmaf(qv, w0.z, acc[2]); acc[3] = fmaf(qv, w0.w, acc[3]);
                acc[4] = fmaf(qv, w1.x, acc[4]); acc[5] = fmaf(qv, w1.y, acc[5]);
                acc[6] = fmaf(qv, w1.z, acc[6]); acc[7] = fmaf(qv, w1.w, acc[7]);
                acc[8] = fmaf(qv, w2.x, acc[8]); acc[9] = fmaf(qv, w2.y, acc[9]);
                acc[10]= fmaf(qv, w2.z, acc[10]);acc[11]= fmaf(qv, w2.w, acc[11]);
            }
        }
    }

    if (t < 128) {
        const int qi = q0 + t;
        const float rx = ref[(size_t)qi*2+0];
        const float ry = ref[(size_t)qi*2+1];
        float v[4], mx = -1e30f;
#pragma unroll
        for (int j=0;j<4;j++) { v[j] = acc[8+j] + bw[j]; mx = fmaxf(mx, v[j]); }
        float s = 0.f;
#pragma unroll
        for (int j=0;j<4;j++) { v[j] = __expf(v[j]-mx); s += v[j]; }
        const float inv = 1.f / s;

        float o[12];
        float wacc = 0.f;
#pragma unroll
        for (int sI=0; sI<4; sI++) {
            const float ox = tanhf(acc[2*sI+0] + bo[2*sI+0]) * OFFSET_SCALE;
            const float oy = tanhf(acc[2*sI+1] + bo[2*sI+1]) * OFFSET_SCALE;
            const float gx = fminf(fmaxf(rx + ox, -1.2f), 1.2f);
            const float gy = fminf(fmaxf(ry + oy, -1.2f), 1.2f);
            const float w  = v[sI] * inv;
            o[sI*3+0] = gx;
            o[sI*3+1] = gy;
            o[sI*3+2] = w;
            // wsum: same corner-weight arithmetic the sampler uses
            const float x = (gx + 1.f) * 0.5f * (WW - 1);
            const float y = (gy + 1.f) * 0.5f * (HH - 1);
            const float x0f = floorf(x), y0f = floorf(y);
            const int x0 = (int)x0f, y0 = (int)y0f;
            const float wx1 = x - x0f, wy1 = y - y0f;
            const float wx0 = 1.f - wx1, wy0 = 1.f - wy1;
            const int   xs[2]  = {x0, x0+1};
            const int   ys[2]  = {y0, y0+1};
            const float wxs[2] = {wx0, wx1};
            const float wys[2] = {wy0, wy1};
#pragma unroll
            for (int cy=0; cy<2; cy++)
#pragma unroll
                for (int cx=0; cx<2; cx++) {
                    const int xi = xs[cx], yi = ys[cy];
                    if (xi >= 0 && xi < WW && yi >= 0 && yi < HH)
                        wacc += w * wxs[cx] * wys[cy];
                }
        }
        wsum[qi] = mask[qi] ? wacc : 0.f;
        float4* dst = (float4*)(samp + (size_t)qi*12);
        dst[0] = make_float4(o[0], o[1], o[2],  o[3]);
        dst[1] = make_float4(o[4], o[5], o[6],  o[7]);
        dst[2] = make_float4(o[8], o[9], o[10], o[11]);
    }
}

// ------------- gather (sample5-proven loop, no wsum store) -------------------
#define QPW 4
__global__ void __launch_bounds__(256)
sample8_kernel(const __half* __restrict__ fmT, const float* __restrict__ samp,
               const int* __restrict__ mask, __half* __restrict__ ctx)
{
    const int t = threadIdx.x;
    const int wid = t >> 5, lane = t & 31;
    const int d = lane * 8;

    for (int itq = 0; itq < QPW; itq++) {
        const int qi = (blockIdx.x * 8 + wid) * QPW + itq;

        if (!mask[qi]) {
            uint4 z = make_uint4(0,0,0,0);
            *(uint4*)(ctx + (size_t)qi*256 + d) = z;
            continue;
        }

        const float4* spp = (const float4*)(samp + (size_t)qi*12);
        const float4 s0 = spp[0], s1 = spp[1], s2 = spp[2];
        const float sp[12] = { s0.x, s0.y, s0.z, s0.w,
                               s1.x, s1.y, s1.z, s1.w,
                               s2.x, s2.y, s2.z, s2.w };

        const __half* base = fmT + ((((size_t)(qi >> 14)) << 14)) * 256;
        float a8[8] = {0.f,0.f,0.f,0.f,0.f,0.f,0.f,0.f};
#pragma unroll
        for (int s = 0; s < 4; s++) {
            const float gx = sp[s*3+0], gy = sp[s*3+1], w = sp[s*3+2];
            const float x = (gx + 1.f) * 0.5f * (WW - 1);
            const float y = (gy + 1.f) * 0.5f * (HH - 1);
            const float x0f = floorf(x), y0f = floorf(y);
            const int x0 = (int)x0f, y0 = (int)y0f;
            const float wx1 = x - x0f, wy1 = y - y0f;
            const float wx0 = 1.f - wx1, wy0 = 1.f - wy1;
            const int   xs[2]  = {x0, x0+1};
            const int   ys[2]  = {y0, y0+1};
            const float wxs[2] = {wx0, wx1};
            const float wys[2] = {wy0, wy1};
#pragma unroll
            for (int cy=0; cy<2; cy++)
#pragma unroll
                for (int cx=0; cx<2; cx++) {
                    const int xi = xs[cx], yi = ys[cy];
                    if (xi >= 0 && xi < WW && yi >= 0 && yi < HH) {
                        const float cw = w * wxs[cx] * wys[cy];
                        const uint4 vv = *(const uint4*)(base + ((size_t)(yi*WW + xi))*256 + d);
                        const __half2* h = (const __half2*)&vv;
#pragma unroll
                        for (int p = 0; p < 4; p++) {
                            float2 f = __half22float2(h[p]);
                            a8[2*p+0] = fmaf(cw, f.x, a8[2*p+0]);
                            a8[2*p+1] = fmaf(cw, f.y, a8[2*p+1]);
                        }
                    }
                }
        }

        __half2 o0 = __floats2half2_rn(a8[0], a8[1]);
        __half2 o1 = __floats2half2_rn(a8[2], a8[3]);
        __half2 o2 = __floats2half2_rn(a8[4], a8[5]);
        __half2 o3 = __floats2half2_rn(a8[6], a8[7]);
        uint4 o;
        o.x = *(unsigned*)&o0; o.y = *(unsigned*)&o1;
        o.z = *(unsigned*)&o2; o.w = *(unsigned*)&o3;
        *(uint4*)(ctx + (size_t)qi*256 + d) = o;
    }
}

// -----------------------------------------------------------------------------
extern "C" void kernel_launch(void* const* d_in, const int* in_sizes, int n_in,
                              void* d_out, int out_size)
{
    const float* queries  = (const float*)d_in[0];
    const float* ref_pts  = (const float*)d_in[1];
    const float* fmap     = (const float*)d_in[2];
    const int*   vmask    = (const int*)  d_in[3];
    const float* Wq = (const float*)d_in[4];
    const float* bq = (const float*)d_in[5];
    const float* Wf = (const float*)d_in[6];
    const float* bf = (const float*)d_in[7];
    const float* Wo = (const float*)d_in[8];
    const float* bo = (const float*)d_in[9];
    const float* Ww = (const float*)d_in[10];
    const float* bw = (const float*)d_in[11];
    const float* W1 = (const float*)d_in[12];
    const float* b1 = (const float*)d_in[13];
    const float* W2 = (const float*)d_in[14];
    const float* b2 = (const float*)d_in[15];
    float* out = (float*)d_out;

    __half *fmT, *qh, *ctxh, *h1h, *Wch, *W2h;
    float *samp, *wsum, *cvec, *dvec;
    cudaGetSymbolAddress((void**)&fmT,  g_fmT);
    cudaGetSymbolAddress((void**)&qh,   g_qh);
    cudaGetSymbolAddress((void**)&ctxh, g_ctx);
    cudaGetSymbolAddress((void**)&h1h,  g_h1);
    cudaGetSymbolAddress((void**)&samp, g_samp);
    cudaGetSymbolAddress((void**)&wsum, g_wsum);
    cudaGetSymbolAddress((void**)&Wch,  g_Wch);
    cudaGetSymbolAddress((void**)&W2h,  g_W2h);
    cudaGetSymbolAddress((void**)&cvec, g_cvec);
    cudaGetSymbolAddress((void**)&dvec, g_dvec);

    // one-time setup: smem attr + side streams/events (host-side, no device mem)
    static cudaStream_t sA = nullptr, sB = nullptr;
    static cudaEvent_t evR = nullptr, evA = nullptr, evB = nullptr;
    if (!sA) {
        cudaFuncSetAttribute(gemm_c<2, __half, true>,
                             cudaFuncAttributeMaxDynamicSharedMemorySize, GEMM_SMEM);
        cudaFuncSetAttribute(gemm_c<0, float, false>,
                             cudaFuncAttributeMaxDynamicSharedMemorySize, GEMM_SMEM);
        cudaStreamCreateWithFlags(&sA, cudaStreamNonBlocking);
        cudaStreamCreateWithFlags(&sB, cudaStreamNonBlocking);
        cudaEventCreateWithFlags(&evR, cudaEventDisableTiming);
        cudaEventCreateWithFlags(&evA, cudaEventDisableTiming);
        cudaEventCreateWithFlags(&evB, cudaEventDisableTiming);
    }

    const dim3 gGemm(256/128, MTOT/128);    // (2, 512)
    const dim3 gTr(HWSZ/32, 256/32, BB);    // (512, 8, 4)

    // fork: transpose on sA, prep on sB, offw6 on the main stream
    cudaEventRecord(evR, 0);
    cudaStreamWaitEvent(sA, evR, 0);
    cudaStreamWaitEvent(sB, evR, 0);
    transpose_h<<<gTr, 256, 0, sA>>>(fmap, fmT);
    prep_kernel<<<578, 256, 0, sB>>>(Wq, Wf, W1, W2, bq, bf, W2h, Wch, cvec, dvec);
    offw6_kernel<<<MTOT/128, 256>>>(queries, Wo, bo, Ww, bw, ref_pts, vmask,
                                    samp, wsum, qh);
    // join
    cudaEventRecord(evA, sA);
    cudaEventRecord(evB, sB);
    cudaStreamWaitEvent(0, evA, 0);
    cudaStreamWaitEvent(0, evB, 0);

    // gather -> ctx_raw fp16 (masked)
    sample8_kernel<<<MTOT/(8*QPW), 256>>>(fmT, samp, vmask, ctxh);
    // h1 = relu(qh@Wc + ctx_raw@Wf1 + b1 + m*cvec + wsum*dvec)
    gemm_c<2, __half, true><<<gGemm, 256, GEMM_SMEM>>>(
        qh, ctxh, Wch, b1, cvec, dvec, vmask, wsum, h1h, 512, 1);
    // out = h1 @ W2 + b2
    gemm_c<0, float, false><<<gGemm, 256, GEMM_SMEM>>>(
        h1h, nullptr, W2h, b2, nullptr, nullptr, nullptr, nullptr, out, 256, 0);
}

// round 16
// speedup vs baseline: 1.1121x; 1.0397x over previous
#include <cuda_runtime.h>
#include <cuda_fp16.h>
#include <cuda_bf16.h>
#include <math.h>

// Problem constants
#define BB 4
#define QQ 16384
#define SS 4
#define HD 256
#define HH 128
#define WW 128
#define HWSZ (HH*WW)          // 16384
#define MTOT (BB*QQ)          // 65536
#define OFFSET_SCALE 0.05f

// ---------------- scratch (device globals; no runtime alloc allowed) ----------
__device__ __half g_fmT[(size_t)BB*HWSZ*HD];  // fmap HWC fp16   33.5MB
__device__ __half g_qh [(size_t)MTOT*HD];     // masked q fp16   33.5MB
__device__ __half g_ctx[(size_t)MTOT*HD];     // ctx_raw (masked) 33.5MB
__device__ __half g_part[(size_t)MTOT*HD];    // qh@Wc_top fp16  33.5MB
__device__ __half g_h1 [(size_t)MTOT*HD];     // relu(...)       33.5MB
__device__ float  g_samp[(size_t)MTOT*12];    // per query: (gx,gy,w)x4
__device__ float  g_wsum[(size_t)MTOT];       // per query bilinear weight sum
__device__ __half g_Wch[512*256];             // [Wq@W1top ; Wf@W1bot] fp16
__device__ __half g_W2h[256*256];
__device__ float  g_cvec[256];                // bq@W1top
__device__ float  g_dvec[256];                // bf@W1bot
__device__ float  g_zero[256];                // zeros (bss)

// ---------------- mma / ldmatrix / cp.async helpers --------------------------
__device__ __forceinline__ void hmma16(float* c,
                                       unsigned a0, unsigned a1, unsigned a2, unsigned a3,
                                       unsigned b0, unsigned b1) {
    asm volatile(
        "mma.sync.aligned.m16n8k16.row.col.f32.f16.f16.f32 "
        "{%0,%1,%2,%3},{%4,%5,%6,%7},{%8,%9},{%0,%1,%2,%3};"
        : "+f"(c[0]), "+f"(c[1]), "+f"(c[2]), "+f"(c[3])
        : "r"(a0), "r"(a1), "r"(a2), "r"(a3), "r"(b0), "r"(b1));
}
__device__ __forceinline__ void ldsm4(unsigned& r0, unsigned& r1, unsigned& r2, unsigned& r3,
                                      unsigned addr) {
    asm volatile("ldmatrix.sync.aligned.m8n8.x4.shared.b16 {%0,%1,%2,%3}, [%4];"
                 : "=r"(r0), "=r"(r1), "=r"(r2), "=r"(r3) : "r"(addr));
}
__device__ __forceinline__ void ldsm4t(unsigned& r0, unsigned& r1, unsigned& r2, unsigned& r3,
                                       unsigned addr) {
    asm volatile("ldmatrix.sync.aligned.m8n8.x4.trans.shared.b16 {%0,%1,%2,%3}, [%4];"
                 : "=r"(r0), "=r"(r1), "=r"(r2), "=r"(r3) : "r"(addr));
}
__device__ __forceinline__ void cp16(void* dst, const void* src) {
    unsigned d = (unsigned)__cvta_generic_to_shared(dst);
    asm volatile("cp.async.cg.shared.global [%0], [%1], 16;" :: "r"(d), "l"(src));
}
__device__ __forceinline__ void cp_commit() { asm volatile("cp.async.commit_group;"); }
__device__ __forceinline__ void cp_wait0()  { asm volatile("cp.async.wait_group 0;"); }
__device__ __forceinline__ void cp_wait1()  { asm volatile("cp.async.wait_group 1;"); }

#define LDAH 40     // m-major A stride (halfs): 5x16B units -> LDSM conflict-free
#define LDBH 136    // k-major stride (halfs): 17x16B units -> LDSM conflict-free
#define NSTG 3
#define A_STAGE (128*LDAH)
#define B_STAGE (32*LDBH)
#define GEMM_SMEM ((NSTG*(A_STAGE + B_STAGE)) * 2)   // bytes = 56832

// ---------------- merged precompute kernel -----------------------------------
__global__ void __launch_bounds__(256)
prep_kernel(const float* __restrict__ Wq, const float* __restrict__ Wf,
            const float* __restrict__ W1, const float* __restrict__ W2,
            const float* __restrict__ bq, const float* __restrict__ bf,
            __half* __restrict__ oW2, __half* __restrict__ Wcomb,
            float* __restrict__ cvec, float* __restrict__ dvec)
{
    const int bi = blockIdx.x;
    const int t  = threadIdx.x;
    if (bi < 64) {
        const int idx = bi*256 + t;
        float4 v = ((const float4*)W2)[idx];
        ((__half2*)oW2)[idx*2+0] = __floats2half2_rn(v.x, v.y);
        ((__half2*)oW2)[idx*2+1] = __floats2half2_rn(v.z, v.w);
    } else if (bi < 576) {
        const int r = bi - 64;           // 0..511
        const float* arow  = (r < 256) ? (Wq + r*256) : (Wf + (r-256)*256);
        const float* Bbase = (r < 256) ? W1 : (W1 + 256*256);
        __shared__ float a[256];
        a[t] = arow[t];
        __syncthreads();
        float acc = 0.f;
#pragma unroll 4
        for (int k = 0; k < 256; k++) acc = fmaf(a[k], Bbase[k*256 + t], acc);
        Wcomb[r*256 + t] = __float2half_rn(acc);
    } else {
        const float* bv    = (bi == 576) ? bq : bf;
        const float* Bbase = (bi == 576) ? W1 : (W1 + 256*256);
        float* outv        = (bi == 576) ? cvec : dvec;
        float acc = 0.f;
#pragma unroll 4
        for (int k = 0; k < 256; k++) acc = fmaf(bv[k], Bbase[k*256 + t], acc);
        outv[t] = acc;
    }
}

// ---------------- CHW fp32 -> HWC fp16 transpose -----------------------------
__global__ void __launch_bounds__(256)
transpose_h(const float* __restrict__ fm, __half* __restrict__ fmT)
{
    __shared__ float ts[32][33];
    const int b  = blockIdx.z;
    const int c0 = blockIdx.y * 32;
    const int h0 = blockIdx.x * 32;
    const int t  = threadIdx.x;

    {
        const int cl = t >> 3, h4 = (t & 7) * 4;
        float4 v = *(const float4*)(fm + ((size_t)(b*256 + c0 + cl)) * HWSZ + h0 + h4);
        ts[h4+0][cl] = v.x; ts[h4+1][cl] = v.y; ts[h4+2][cl] = v.z; ts[h4+3][cl] = v.w;
    }
    __syncthreads();
    {
        const int hl = t >> 3, c4 = (t & 7) * 4;
        __half2 o0 = __floats2half2_rn(ts[hl][c4+0], ts[hl][c4+1]);
        __half2 o1 = __floats2half2_rn(ts[hl][c4+2], ts[hl][c4+3]);
        __half2* dst = (__half2*)(fmT + ((size_t)((b << 14) + h0 + hl)) * 256 + c0 + c4);
        dst[0] = o0; dst[1] = o1;
    }
}

// ---------------- GEMM: K=256, 3-stage cp.async, fp16 A ----------------------
// EXT: + msk*cvec + wsum*dvec in epilogue.  ADDP: + Part[m][n] (fp16) before relu.
template<typename TC, bool EXT, bool ADDP>
__global__ void __launch_bounds__(256, 2)
gemm_c(const __half* __restrict__ A0, const __half* __restrict__ Wh,
       const float* __restrict__ Bias,
       const float* __restrict__ cvec, const float* __restrict__ dvec,
       const int* __restrict__ mask, const float* __restrict__ wsum,
       const __half* __restrict__ Part,
       TC* __restrict__ C, int doRelu)
{
    constexpr int N = 256;
    constexpr int K = 256;
    extern __shared__ __half dynsm[];
    __half* AsB = dynsm;
    __half* BsB = dynsm + NSTG * A_STAGE;

    const int t    = threadIdx.x;
    const int m0   = blockIdx.y * 128;
    const int n0   = blockIdx.x * 128;
    const int wid  = t >> 5;
    const int lane = t & 31;
    const int wm   = wid >> 1;
    const int wn   = wid & 1;
    const int g    = lane >> 2;
    const int tig  = lane & 3;

    float acc[2][8][4];
#pragma unroll
    for (int i=0;i<2;i++)
#pragma unroll
        for (int j=0;j<8;j++)
#pragma unroll
            for (int l=0;l<4;l++) acc[i][j][l] = 0.f;

    auto load_tile = [&](int s, int k0) {
        __half* As = AsB + s * A_STAGE;
        __half* Bs = BsB + s * B_STAGE;
#pragma unroll
        for (int i = 0; i < 2; i++) {
            const int idx = t + i * 256;
            const int m   = idx >> 2;
            const int k8  = (idx & 3) * 8;
            cp16(&As[m*LDAH + k8], A0 + (size_t)(m0+m)*256 + k0 + k8);
        }
#pragma unroll
        for (int i = 0; i < 2; i++) {
            const int idx = t + i * 256;
            const int kr  = idx >> 4;
            const int n8  = (idx & 15) * 8;
            cp16(&Bs[kr*LDBH + n8], Wh + (size_t)(k0+kr)*N + n0 + n8);
        }
        cp_commit();
    };

    auto compute = [&](int s) {
        __half* As = AsB + s * A_STAGE;
        __half* Bs = BsB + s * B_STAGE;
#pragma unroll
        for (int ks = 0; ks < 2; ks++) {
            const int k = ks * 16;
            unsigned a[2][4], b[8][2];
#pragma unroll
            for (int mt = 0; mt < 2; mt++) {
                const int row = wm*32 + mt*16 + (lane & 15);
                const int col = k + ((lane >> 4) << 3);
                unsigned addr = (unsigned)__cvta_generic_to_shared(&As[row*LDAH + col]);
                ldsm4(a[mt][0], a[mt][1], a[mt][2], a[mt][3], addr);
            }
#pragma unroll
            for (int p = 0; p < 4; p++) {
                const int rowB = k + (lane & 15);
                const int colB = wn*64 + p*16 + ((lane >> 4) << 3);
                unsigned addr = (unsigned)__cvta_generic_to_shared(&Bs[rowB*LDBH + colB]);
                ldsm4t(b[2*p][0], b[2*p][1], b[2*p+1][0], b[2*p+1][1], addr);
            }
#pragma unroll
            for (int mt = 0; mt < 2; mt++)
#pragma unroll
                for (int nt = 0; nt < 8; nt++)
                    hmma16(acc[mt][nt], a[mt][0], a[mt][1], a[mt][2], a[mt][3],
                           b[nt][0], b[nt][1]);
        }
    };

    const int nK = K / 32;   // 8
    load_tile(0, 0);
    load_tile(1, 32);
    for (int it = 0; it < nK; ++it) {
        if (it + 1 < nK) cp_wait1(); else cp_wait0();
        __syncthreads();
        if (it + 2 < nK) load_tile((it+2)%NSTG, (it+2)*32);
        compute(it % NSTG);
    }

#pragma unroll
    for (int mt = 0; mt < 2; mt++) {
        const int r0 = m0 + wm*32 + mt*16 + g;
        const int r1 = r0 + 8;
        float msk0 = 0.f, msk1 = 0.f, ws0 = 0.f, ws1 = 0.f;
        if (EXT) {
            msk0 = mask[r0] ? 1.f : 0.f;
            msk1 = mask[r1] ? 1.f : 0.f;
            ws0 = wsum[r0]; ws1 = wsum[r1];
        }
#pragma unroll
        for (int nt = 0; nt < 8; nt++) {
            const int c = n0 + wn*64 + nt*8 + tig*2;
            const float bb0 = Bias[c], bb1 = Bias[c+1];
            float v00 = acc[mt][nt][0] + bb0;
            float v01 = acc[mt][nt][1] + bb1;
            float v10 = acc[mt][nt][2] + bb0;
            float v11 = acc[mt][nt][3] + bb1;
            if (EXT) {
                const float cv0 = cvec[c], cv1 = cvec[c+1];
                const float dv0 = dvec[c], dv1 = dvec[c+1];
                v00 += msk0*cv0 + ws0*dv0;  v01 += msk0*cv1 + ws0*dv1;
                v10 += msk1*cv0 + ws1*dv0;  v11 += msk1*cv1 + ws1*dv1;
            }
            if (ADDP) {
                float2 p0 = __half22float2(*(const __half2*)(Part + (size_t)r0*N + c));
                float2 p1 = __half22float2(*(const __half2*)(Part + (size_t)r1*N + c));
                v00 += p0.x; v01 += p0.y;
                v10 += p1.x; v11 += p1.y;
            }
            if (doRelu) {
                v00 = fmaxf(v00, 0.f); v01 = fmaxf(v01, 0.f);
                v10 = fmaxf(v10, 0.f); v11 = fmaxf(v11, 0.f);
            }
            if constexpr (sizeof(TC) == 2) {
                *(__half2*)((__half*)C + (size_t)r0*N + c) = __floats2half2_rn(v00, v01);
                *(__half2*)((__half*)C + (size_t)r1*N + c) = __floats2half2_rn(v10, v11);
            } else {
                *(float2*)((float*)C + (size_t)r0*N + c) = make_float2(v00, v01);
                *(float2*)((float*)C + (size_t)r1*N + c) = make_float2(v10, v11);
            }
        }
    }
}

// ------------- offsets + softmax + postprocess + wsum + masked qh fp16 -------
__global__ void __launch_bounds__(256)
offw6_kernel(const float* __restrict__ q,
             const float* __restrict__ Wo, const float* __restrict__ bo,
             const float* __restrict__ Ww, const float* __restrict__ bw,
             const float* __restrict__ ref, const int* __restrict__ mask,
             float* __restrict__ samp, float* __restrict__ wsum,
             __half* __restrict__ qh)
{
    __shared__ float wcat[256*12];
    __shared__ float qs[128*33];

    const int t  = threadIdx.x;
    const int q0 = blockIdx.x * 128;

    {
        float4 w0 = *(const float4*)(Wo + t*8);
        float4 w1 = *(const float4*)(Wo + t*8 + 4);
        float4 w2 = *(const float4*)(Ww + t*4);
        *(float4*)&wcat[t*12 + 0] = w0;
        *(float4*)&wcat[t*12 + 4] = w1;
        *(float4*)&wcat[t*12 + 8] = w2;
    }

    float acc[12];
#pragma unroll
    for (int j = 0; j < 12; j++) acc[j] = 0.f;

    for (int k0 = 0; k0 < 256; k0 += 32) {
        __syncthreads();
#pragma unroll
        for (int i = 0; i < 4; i++) {
            const int idx4 = i*256 + t;
            const int row  = idx4 >> 3;
            const int c4   = (idx4 & 7) * 4;
            float4 v = *(const float4*)(q + (size_t)(q0+row)*256 + k0 + c4);
            qs[row*33 + c4 + 0] = v.x; qs[row*33 + c4 + 1] = v.y;
            qs[row*33 + c4 + 2] = v.z; qs[row*33 + c4 + 3] = v.w;
            const float mk = mask[q0+row] ? 1.f : 0.f;
            __half2* dst = (__half2*)(qh + (size_t)(q0+row)*256 + k0 + c4);
            dst[0] = __floats2half2_rn(v.x*mk, v.y*mk);
            dst[1] = __floats2half2_rn(v.z*mk, v.w*mk);
        }
        __syncthreads();
        if (t < 128) {
#pragma unroll
            for (int kk = 0; kk < 32; kk++) {
                const float qv = qs[t*33 + kk];
                const float4 w0 = *(const float4*)&wcat[(k0+kk)*12 + 0];
                const float4 w1 = *(const float4*)&wcat[(k0+kk)*12 + 4];
                const float4 w2 = *(const float4*)&wcat[(k0+kk)*12 + 8];
                acc[0] = fmaf(qv, w0.x, acc[0]); acc[1] = fmaf(qv, w0.y, acc[1]);
                acc[2] = fmaf(qv, w0.z, acc[2]); acc[3] = fmaf(qv, w0.w, acc[3]);
                acc[4] = fmaf(qv, w1.x, acc[4]); acc[5] = fmaf(qv, w1.y, acc[5]);
                acc[6] = fmaf(qv, w1.z, acc[6]); acc[7] = fmaf(qv, w1.w, acc[7]);
                acc[8] = fmaf(qv, w2.x, acc[8]); acc[9] = fmaf(qv, w2.y, acc[9]);
                acc[10]= fmaf(qv, w2.z, acc[10]);acc[11]= fmaf(qv, w2.w, acc[11]);
            }
        }
    }

    if (t < 128) {
        const int qi = q0 + t;
        const float rx = ref[(size_t)qi*2+0];
        const float ry = ref[(size_t)qi*2+1];
        float v[4], mx = -1e30f;
#pragma unroll
        for (int j=0;j<4;j++) { v[j] = acc[8+j] + bw[j]; mx = fmaxf(mx, v[j]); }
        float s = 0.f;
#pragma unroll
        for (int j=0;j<4;j++) { v[j] = __expf(v[j]-mx); s += v[j]; }
        const float inv = 1.f / s;

        float o[12];
        float wacc = 0.f;
#pragma unroll
        for (int sI=0; sI<4; sI++) {
            const float ox = tanhf(acc[2*sI+0] + bo[2*sI+0]) * OFFSET_SCALE;
            const float oy = tanhf(acc[2*sI+1] + bo[2*sI+1]) * OFFSET_SCALE;
            const float gx = fminf(fmaxf(rx + ox, -1.2f), 1.2f);
            const float gy = fminf(fmaxf(ry + oy, -1.2f), 1.2f);
            const float w  = v[sI] * inv;
            o[sI*3+0] = gx;
            o[sI*3+1] = gy;
            o[sI*3+2] = w;
            const float x = (gx + 1.f) * 0.5f * (WW - 1);
            const float y = (gy + 1.f) * 0.5f * (HH - 1);
            const float x0f = floorf(x), y0f = floorf(y);
            const int x0 = (int)x0f, y0 = (int)y0f;
            const float wx1 = x - x0f, wy1 = y - y0f;
            const float wx0 = 1.f - wx1, wy0 = 1.f - wy1;
            const int   xs[2]  = {x0, x0+1};
            const int   ys[2]  = {y0, y0+1};
            const float wxs[2] = {wx0, wx1};
            const float wys[2] = {wy0, wy1};
#pragma unroll
            for (int cy=0; cy<2; cy++)
#pragma unroll
                for (int cx=0; cx<2; cx++) {
                    const int xi = xs[cx], yi = ys[cy];
                    if (xi >= 0 && xi < WW && yi >= 0 && yi < HH)
                        wacc += w * wxs[cx] * wys[cy];
                }
        }
        wsum[qi] = mask[qi] ? wacc : 0.f;
        float4* dst = (float4*)(samp + (size_t)qi*12);
        dst[0] = make_float4(o[0], o[1], o[2],  o[3]);
        dst[1] = make_float4(o[4], o[5], o[6],  o[7]);
        dst[2] = make_float4(o[8], o[9], o[10], o[11]);
    }
}

// ------------- gather (proven sample8 loop) ----------------------------------
#define QPW 4
__global__ void __launch_bounds__(256)
sample8_kernel(const __half* __restrict__ fmT, const float* __restrict__ samp,
               const int* __restrict__ mask, __half* __restrict__ ctx)
{
    const int t = threadIdx.x;
    const int wid = t >> 5, lane = t & 31;
    const int d = lane * 8;

    for (int itq = 0; itq < QPW; itq++) {
        const int qi = (blockIdx.x * 8 + wid) * QPW + itq;

        if (!mask[qi]) {
            uint4 z = make_uint4(0,0,0,0);
            *(uint4*)(ctx + (size_t)qi*256 + d) = z;
            continue;
        }

        const float4* spp = (const float4*)(samp + (size_t)qi*12);
        const float4 s0 = spp[0], s1 = spp[1], s2 = spp[2];
        const float sp[12] = { s0.x, s0.y, s0.z, s0.w,
                               s1.x, s1.y, s1.z, s1.w,
                               s2.x, s2.y, s2.z, s2.w };

        const __half* base = fmT + ((((size_t)(qi >> 14)) << 14)) * 256;
        float a8[8] = {0.f,0.f,0.f,0.f,0.f,0.f,0.f,0.f};
#pragma unroll
        for (int s = 0; s < 4; s++) {
            const float gx = sp[s*3+0], gy = sp[s*3+1], w = sp[s*3+2];
            const float x = (gx + 1.f) * 0.5f * (WW - 1);
            const float y = (gy + 1.f) * 0.5f * (HH - 1);
            const float x0f = floorf(x), y0f = floorf(y);
            const int x0 = (int)x0f, y0 = (int)y0f;
            const float wx1 = x - x0f, wy1 = y - y0f;
            const float wx0 = 1.f - wx1, wy0 = 1.f - wy1;
            const int   xs[2]  = {x0, x0+1};
            const int   ys[2]  = {y0, y0+1};
            const float wxs[2] = {wx0, wx1};
            const float wys[2] = {wy0, wy1};
#pragma unroll
            for (int cy=0; cy<2; cy++)
#pragma unroll
                for (int cx=0; cx<2; cx++) {
                    const int xi = xs[cx], yi = ys[cy];
                    if (xi >= 0 && xi < WW && yi >= 0 && yi < HH) {
                        const float cw = w * wxs[cx] * wys[cy];
                        const uint4 vv = *(const uint4*)(base + ((size_t)(yi*WW + xi))*256 + d);
                        const __half2* h = (const __half2*)&vv;
#pragma unroll
                        for (int p = 0; p < 4; p++) {
                            float2 f = __half22float2(h[p]);
                            a8[2*p+0] = fmaf(cw, f.x, a8[2*p+0]);
                            a8[2*p+1] = fmaf(cw, f.y, a8[2*p+1]);
                        }
                    }
                }
        }

        __half2 o0 = __floats2half2_rn(a8[0], a8[1]);
        __half2 o1 = __floats2half2_rn(a8[2], a8[3]);
        __half2 o2 = __floats2half2_rn(a8[4], a8[5]);
        __half2 o3 = __floats2half2_rn(a8[6], a8[7]);
        uint4 o;
        o.x = *(unsigned*)&o0; o.y = *(unsigned*)&o1;
        o.z = *(unsigned*)&o2; o.w = *(unsigned*)&o3;
        *(uint4*)(ctx + (size_t)qi*256 + d) = o;
    }
}

// -----------------------------------------------------------------------------
extern "C" void kernel_launch(void* const* d_in, const int* in_sizes, int n_in,
                              void* d_out, int out_size)
{
    const float* queries  = (const float*)d_in[0];
    const float* ref_pts  = (const float*)d_in[1];
    const float* fmap     = (const float*)d_in[2];
    const int*   vmask    = (const int*)  d_in[3];
    const float* Wq = (const float*)d_in[4];
    const float* bq = (const float*)d_in[5];
    const float* Wf = (const float*)d_in[6];
    const float* bf = (const float*)d_in[7];
    const float* Wo = (const float*)d_in[8];
    const float* bo = (const float*)d_in[9];
    const float* Ww = (const float*)d_in[10];
    const float* bw = (const float*)d_in[11];
    const float* W1 = (const float*)d_in[12];
    const float* b1 = (const float*)d_in[13];
    const float* W2 = (const float*)d_in[14];
    const float* b2 = (const float*)d_in[15];
    float* out = (float*)d_out;

    __half *fmT, *qh, *ctxh, *parth, *h1h, *Wch, *W2h;
    float *samp, *wsum, *cvec, *dvec, *zvec;
    cudaGetSymbolAddress((void**)&fmT,   g_fmT);
    cudaGetSymbolAddress((void**)&qh,    g_qh);
    cudaGetSymbolAddress((void**)&ctxh,  g_ctx);
    cudaGetSymbolAddress((void**)&parth, g_part);
    cudaGetSymbolAddress((void**)&h1h,   g_h1);
    cudaGetSymbolAddress((void**)&samp,  g_samp);
    cudaGetSymbolAddress((void**)&wsum,  g_wsum);
    cudaGetSymbolAddress((void**)&Wch,   g_Wch);
    cudaGetSymbolAddress((void**)&W2h,   g_W2h);
    cudaGetSymbolAddress((void**)&cvec,  g_cvec);
    cudaGetSymbolAddress((void**)&dvec,  g_dvec);
    cudaGetSymbolAddress((void**)&zvec,  g_zero);

    // one-time setup: smem attr + side streams/events (host-side, no device mem)
    static cudaStream_t sA = nullptr, sB = nullptr;
    static cudaEvent_t evR = nullptr, evA = nullptr, evB = nullptr;
    static cudaEvent_t evQ = nullptr, evP = nullptr;
    if (!sA) {
        cudaFuncSetAttribute(gemm_c<__half, false, false>,
                             cudaFuncAttributeMaxDynamicSharedMemorySize, GEMM_SMEM);
        cudaFuncSetAttribute(gemm_c<__half, true, true>,
                             cudaFuncAttributeMaxDynamicSharedMemorySize, GEMM_SMEM);
        cudaFuncSetAttribute(gemm_c<float, false, false>,
                             cudaFuncAttributeMaxDynamicSharedMemorySize, GEMM_SMEM);
        cudaStreamCreateWithFlags(&sA, cudaStreamNonBlocking);
        cudaStreamCreateWithFlags(&sB, cudaStreamNonBlocking);
        cudaEventCreateWithFlags(&evR, cudaEventDisableTiming);
        cudaEventCreateWithFlags(&evA, cudaEventDisableTiming);
        cudaEventCreateWithFlags(&evB, cudaEventDisableTiming);
        cudaEventCreateWithFlags(&evQ, cudaEventDisableTiming);
        cudaEventCreateWithFlags(&evP, cudaEventDisableTiming);
    }

    const dim3 gGemm(256/128, MTOT/128);    // (2, 512)
    const dim3 gTr(HWSZ/32, 256/32, BB);    // (512, 8, 4)

    // fork: transpose on sA, prep on sB, offw6 on main
    cudaEventRecord(evR, 0);
    cudaStreamWaitEvent(sA, evR, 0);
    cudaStreamWaitEvent(sB, evR, 0);
    transpose_h<<<gTr, 256, 0, sA>>>(fmap, fmT);
    cudaEventRecord(evA, sA);
    prep_kernel<<<578, 256, 0, sB>>>(Wq, Wf, W1, W2, bq, bf, W2h, Wch, cvec, dvec);
    cudaEventRecord(evB, sB);
    offw6_kernel<<<MTOT/128, 256>>>(queries, Wo, bo, Ww, bw, ref_pts, vmask,
                                    samp, wsum, qh);
    cudaEventRecord(evQ, 0);

    // sA: part = qh @ Wc_top  (needs offw6's qh + prep's Wch) — runs concurrent
    // with sample8 on the main stream.
    cudaStreamWaitEvent(sA, evQ, 0);
    cudaStreamWaitEvent(sA, evB, 0);
    gemm_c<__half, false, false><<<gGemm, 256, GEMM_SMEM, sA>>>(
        qh, Wch, zvec, nullptr, nullptr, nullptr, nullptr, nullptr, parth, 0);
    cudaEventRecord(evP, sA);

    // main: gather (needs transpose + offw6)
    cudaStreamWaitEvent(0, evA, 0);
    sample8_kernel<<<MTOT/(8*QPW), 256>>>(fmT, samp, vmask, ctxh);

    // join: part must be done before part2
    cudaStreamWaitEvent(0, evP, 0);
    // h1 = relu(part + ctx@Wc_bot + b1 + m*cvec + ws*dvec)
    gemm_c<__half, true, true><<<gGemm, 256, GEMM_SMEM>>>(
        ctxh, Wch + 256*256, b1, cvec, dvec, vmask, wsum, parth, h1h, 1);
    // out = h1 @ W2 + b2
    gemm_c<float, false, false><<<gGemm, 256, GEMM_SMEM>>>(
        h1h, W2h, b2, nullptr, nullptr, nullptr, nullptr, nullptr, out, 0);
}